// round 1
// baseline (speedup 1.0000x reference)
#include <cuda_runtime.h>

// SimpleDistanceLoss: sum over rows of min over cols of ||a_r - b_c||^2
// = sum_r ( a2[r] + min_c ( b2[c] - 2 * <a_r, b_c> ) )
//
// N = M = 16384, D = 64, fp32.

#define NPTS    16384
#define DDIM    64
#define BM      128
#define BN      128
#define NTILES  (NPTS / BN)   // 128
#define NBLK    (NPTS / BM)   // 128

// Scratch (no device allocation allowed)
__device__ float g_asq[NPTS];
__device__ float g_bsq[NPTS];
__device__ float g_bsum[NBLK];

static __device__ __forceinline__ unsigned long long fma2(unsigned long long a,
                                                          unsigned long long b,
                                                          unsigned long long c) {
    unsigned long long d;
    asm("fma.rn.f32x2 %0, %1, %2, %3;" : "=l"(d) : "l"(a), "l"(b), "l"(c));
    return d;
}
static __device__ __forceinline__ void unpack2(unsigned long long v, float& x, float& y) {
    asm("mov.b64 {%0, %1}, %2;" : "=f"(x), "=f"(y) : "l"(v));
}

// ---------------------------------------------------------------------------
// Squared norms of 16384 x 64 rows. sel==0 -> g_asq, sel==1 -> g_bsq.
// ---------------------------------------------------------------------------
__global__ void sqnorm_kernel(const float* __restrict__ P, int sel) {
    int r = blockIdx.x * blockDim.x + threadIdx.x;
    const float4* p = reinterpret_cast<const float4*>(P) + (size_t)r * (DDIM / 4);
    float s = 0.f;
#pragma unroll
    for (int i = 0; i < DDIM / 4; i++) {
        float4 v = p[i];
        s += v.x * v.x + v.y * v.y + v.z * v.z + v.w * v.w;
    }
    if (sel) g_bsq[r] = s; else g_asq[r] = s;
}

// ---------------------------------------------------------------------------
// Main kernel: each CTA owns BM=128 rows, streams all 16384 cols in BN=128
// tiles. 256 threads, 8x8 register tile per thread via packed f32x2 FMA:
//   acc_pair(c0,c1) += (a,a) * (b_c0, b_c1)      -> 32 FFMA2 per k-step
// A tile in SMEM: k-major, each value duplicated as float2 (so the (a,a)
// operand is a plain vector load, zero pack instructions).
// B tile in SMEM: k-major with XOR swizzle on 4-float chunks so both the
// transpose store and the compute loads avoid heavy bank conflicts.
// ---------------------------------------------------------------------------
#define SMEM_A_BYTES (DDIM * BM * 8)             // 65536: float2[64][128]
#define SMEM_B_BYTES (DDIM * BN * 4)             // 32768: float [64][128]
#define SMEM_BYTES   (SMEM_A_BYTES + SMEM_B_BYTES + (BN + 16) * 4)

__global__ __launch_bounds__(256, 1)
void dist_min_kernel(const float* __restrict__ A, const float* __restrict__ B) {
    extern __shared__ char smem[];
    float2* As2   = reinterpret_cast<float2*>(smem);                    // [64][128] dup pairs
    float*  Bs    = reinterpret_cast<float*>(smem + SMEM_A_BYTES);      // [64][128] swizzled
    float*  bsq_s = reinterpret_cast<float*>(smem + SMEM_A_BYTES + SMEM_B_BYTES);
    float*  red   = bsq_s + BN;                                         // [16]

    const int tid = threadIdx.x;
    const int tx  = tid & 15;          // col group: cols 4*tx..+3 and 64+4*tx..+3
    const int ty  = tid >> 4;          // row group: rows 4*ty..+3 and 64+4*ty..+3
    const int rowbase = blockIdx.x * BM;

    // --- Load A tile once: k-major, duplicated pairs (coalesced gmem read) ---
#pragma unroll
    for (int i = 0; i < 8; i++) {
        int idx4 = tid + i * 256;                 // 2048 float4s
        int row  = idx4 >> 4;
        int k4   = idx4 & 15;
        float4 v = reinterpret_cast<const float4*>(A)[(size_t)(rowbase + row) * (DDIM / 4) + k4];
        As2[(k4 * 4 + 0) * BM + row] = make_float2(v.x, v.x);
        As2[(k4 * 4 + 1) * BM + row] = make_float2(v.y, v.y);
        As2[(k4 * 4 + 2) * BM + row] = make_float2(v.z, v.z);
        As2[(k4 * 4 + 3) * BM + row] = make_float2(v.w, v.w);
    }

    float m[8];
#pragma unroll
    for (int r = 0; r < 8; r++) m[r] = 3.4e38f;

    for (int tile = 0; tile < NTILES; tile++) {
        const int colbase = tile * BN;
        __syncthreads();   // protects Bs/bsq_s from previous iteration's readers

        // --- Load B tile: coalesced gmem read, swizzled k-major SMEM store ---
#pragma unroll
        for (int i = 0; i < 8; i++) {
            int idx4 = tid + i * 256;
            int col  = idx4 >> 4;
            int k4g  = idx4 & 15;
            float4 v = reinterpret_cast<const float4*>(B)[(size_t)(colbase + col) * (DDIM / 4) + k4g];
            int pos  = ((((col >> 2) ^ (k4g & 7)) << 2) | (col & 3));
            float* base = &Bs[(k4g * 4) * BN + pos];
            base[0 * BN] = v.x;
            base[1 * BN] = v.y;
            base[2 * BN] = v.z;
            base[3 * BN] = v.w;
        }
        if (tid < BN) bsq_s[tid] = g_bsq[colbase + tid];
        __syncthreads();

        unsigned long long acc[8][4];
#pragma unroll
        for (int r = 0; r < 8; r++)
#pragma unroll
            for (int c = 0; c < 4; c++) acc[r][c] = 0ull;

#pragma unroll 4
        for (int k = 0; k < DDIM; k++) {
            const float2* arow = &As2[k * BM];
            ulonglong2 aA = *reinterpret_cast<const ulonglong2*>(&arow[ty * 4]);
            ulonglong2 aB = *reinterpret_cast<const ulonglong2*>(&arow[ty * 4 + 2]);
            ulonglong2 aC = *reinterpret_cast<const ulonglong2*>(&arow[64 + ty * 4]);
            ulonglong2 aD = *reinterpret_cast<const ulonglong2*>(&arow[64 + ty * 4 + 2]);
            const int s = (k >> 2) & 7;
            const float* brow = &Bs[k * BN];
            ulonglong2 b0 = *reinterpret_cast<const ulonglong2*>(&brow[(tx ^ s) << 2]);
            ulonglong2 b1 = *reinterpret_cast<const ulonglong2*>(&brow[(16 + (tx ^ s)) << 2]);

            unsigned long long av[8] = {aA.x, aA.y, aB.x, aB.y, aC.x, aC.y, aD.x, aD.y};
            unsigned long long bv[4] = {b0.x, b0.y, b1.x, b1.y};
#pragma unroll
            for (int r = 0; r < 8; r++)
#pragma unroll
                for (int c = 0; c < 4; c++)
                    acc[r][c] = fma2(av[r], bv[c], acc[r][c]);
        }

        // --- Tile epilogue: fold b^2 - 2*dot into running row minima ---
#pragma unroll
        for (int r = 0; r < 8; r++) {
#pragma unroll
            for (int c = 0; c < 4; c++) {
                float d0, d1;
                unpack2(acc[r][c], d0, d1);
                int col = (c < 2) ? (4 * tx + 2 * c) : (64 + 4 * tx + 2 * (c - 2));
                m[r] = fminf(m[r], fmaf(-2.f, d0, bsq_s[col]));
                m[r] = fminf(m[r], fmaf(-2.f, d1, bsq_s[col + 1]));
            }
        }
    }

    // --- Reduce minima across the 16 tx lanes (same rows) ---
#pragma unroll
    for (int r = 0; r < 8; r++) {
        m[r] = fminf(m[r], __shfl_xor_sync(0xffffffffu, m[r], 1));
        m[r] = fminf(m[r], __shfl_xor_sync(0xffffffffu, m[r], 2));
        m[r] = fminf(m[r], __shfl_xor_sync(0xffffffffu, m[r], 4));
        m[r] = fminf(m[r], __shfl_xor_sync(0xffffffffu, m[r], 8));
    }
    if (tx == 0) {
        float s = 0.f;
#pragma unroll
        for (int r = 0; r < 8; r++) {
            int row = rowbase + ((r < 4) ? (ty * 4 + r) : (64 + ty * 4 + (r - 4)));
            s += m[r] + g_asq[row];
        }
        red[ty] = s;
    }
    __syncthreads();
    if (tid == 0) {
        float t = 0.f;
#pragma unroll
        for (int i = 0; i < 16; i++) t += red[i];
        g_bsum[blockIdx.x] = t;
    }
}

// ---------------------------------------------------------------------------
// Deterministic final reduction of 128 block sums -> scalar.
// ---------------------------------------------------------------------------
__global__ void final_reduce_kernel(float* __restrict__ out) {
    int lane = threadIdx.x;  // 32 threads
    float v = 0.f;
#pragma unroll
    for (int i = 0; i < NBLK / 32; i++) v += g_bsum[lane + i * 32];
#pragma unroll
    for (int msk = 16; msk; msk >>= 1) v += __shfl_xor_sync(0xffffffffu, v, msk);
    if (lane == 0) out[0] = v;
}

extern "C" void kernel_launch(void* const* d_in, const int* in_sizes, int n_in,
                              void* d_out, int out_size) {
    const float* A = (const float*)d_in[0];   // from_points [16384,64]
    const float* B = (const float*)d_in[1];   // to_points   [16384,64]
    float* out = (float*)d_out;

    cudaFuncSetAttribute(dist_min_kernel,
                         cudaFuncAttributeMaxDynamicSharedMemorySize, SMEM_BYTES);

    sqnorm_kernel<<<NPTS / 256, 256>>>(A, 0);
    sqnorm_kernel<<<NPTS / 256, 256>>>(B, 1);
    dist_min_kernel<<<NBLK, 256, SMEM_BYTES>>>(A, B);
    final_reduce_kernel<<<1, 32>>>(out);
}

// round 3
// speedup vs baseline: 1.6237x; 1.6237x over previous
#include <cuda_runtime.h>
#include <cstdint>

// SimpleDistanceLoss via legacy tensor-core mma.sync (tf32, baseline PTX):
//   D[m][n] = bsq[n] - 2*<a_m, b_n>   (bsq folded in as K=65th column)
//   answer  = sum_m ( asq[m] + min_n D[m][n] )
//
// 128 CTAs; each owns 128 rows, streams 128 tiles of 128 cols.
// Warps 0-3: compute (64x64 register tile each, m16n8k8 tf32 HMMA).
// Warps 4-7: producers (gmem -> fragment-layout smem, double buffered).

#define NPTS    16384
#define DDIM    64
#define BM      128
#define BN      128
#define NTILES  (NPTS / BN)     // 128
#define NBLK    (NPTS / BM)     // 128
#define KSTEPS  9               // 8 real k-steps of 8 + 1 pad step

__device__ float g_atf[NPTS * DDIM];   // tf32(-2*a), row-major
__device__ float g_btf[NPTS * DDIM];   // tf32(b), row-major
__device__ float g_asq[NPTS];          // exact fp32 ||a||^2
__device__ float g_bsq[NPTS];          // tf32(||b||^2)
__device__ float g_bsum[NBLK];

// smem (floats): A region [0, 9216), B stage0 [9216, 18432), B stage1 [18432, 27648),
// red [27648, 27648+136)
#define STAGEF   9216            // floats per operand region: 9 ksteps * 8 blks * 32 units * 4
#define BSTART   9216
#define REDF     27648
#define SMEM_BYTES ((REDF + 136) * 4)

static __device__ __forceinline__ void mma_acc(float& c0, float& c1, float& c2, float& c3,
                                               uint32_t a0, uint32_t a1, uint32_t a2, uint32_t a3,
                                               uint32_t b0, uint32_t b1) {
    asm("mma.sync.aligned.m16n8k8.row.col.f32.tf32.tf32.f32 "
        "{%0,%1,%2,%3},{%4,%5,%6,%7},{%8,%9},{%0,%1,%2,%3};"
        : "+f"(c0), "+f"(c1), "+f"(c2), "+f"(c3)
        : "r"(a0), "r"(a1), "r"(a2), "r"(a3), "r"(b0), "r"(b1));
}
static __device__ __forceinline__ void mma_zero(float& c0, float& c1, float& c2, float& c3,
                                                uint32_t a0, uint32_t a1, uint32_t a2, uint32_t a3,
                                                uint32_t b0, uint32_t b1) {
    asm("mma.sync.aligned.m16n8k8.row.col.f32.tf32.tf32.f32 "
        "{%0,%1,%2,%3},{%4,%5,%6,%7},{%8,%9},{%10,%10,%10,%10};"
        : "=f"(c0), "=f"(c1), "=f"(c2), "=f"(c3)
        : "r"(a0), "r"(a1), "r"(a2), "r"(a3), "r"(b0), "r"(b1), "f"(0.0f));
}

static __device__ __forceinline__ float rna_tf32(float x) {
    uint32_t u;
    asm("cvt.rna.tf32.f32 %0, %1;" : "=r"(u) : "f"(x));
    return __uint_as_float(u);
}

// ---------------------------------------------------------------------------
// Prep: round to tf32 (A scaled by -2), compute norms.
// ---------------------------------------------------------------------------
__global__ void prep_kernel(const float* __restrict__ A, const float* __restrict__ B) {
    int gid = blockIdx.x * blockDim.x + threadIdx.x;   // 0..32767
    bool isA = gid < NPTS;
    int row = gid & (NPTS - 1);
    const float4* s4 = reinterpret_cast<const float4*>(isA ? A : B) + (size_t)row * 16;
    float4* d4 = reinterpret_cast<float4*>(isA ? g_atf : g_btf) + (size_t)row * 16;
    const float sc = isA ? -2.0f : 1.0f;
    float nrm = 0.f;
#pragma unroll
    for (int i = 0; i < 16; i++) {
        float4 v = s4[i];
        nrm += v.x * v.x + v.y * v.y + v.z * v.z + v.w * v.w;
        float4 o;
        o.x = rna_tf32(sc * v.x);
        o.y = rna_tf32(sc * v.y);
        o.z = rna_tf32(sc * v.z);
        o.w = rna_tf32(sc * v.w);
        d4[i] = o;
    }
    if (isA) g_asq[row] = nrm;
    else     g_bsq[row] = rna_tf32(nrm);
}

// Fill one 128-row operand tile (rows src[base..base+127]) into fragment layout.
// Caller thread set: 128 threads, tsub in [0,128).
// Fragment unit (16B) at ((ks*8 + blk)*32 + c*8 + q) holds
//   { X[r][k], X[r][k+4], X[r+8][k], X[r+8][k+4] }  with r = blk*16+q, k = ks*8+c.
static __device__ __forceinline__ void fill_tile(float* dst, const float* __restrict__ src,
                                                 int rowbase, int tsub) {
    const int pr = tsub & 63;
    const int kh = tsub >> 6;          // k-half: ks in [kh*4, kh*4+4)
    const int q  = pr & 7;
    const int blk = pr >> 3;           // 0..7
    const int r0 = blk * 16 + q;
    const float4* s0 = reinterpret_cast<const float4*>(src) + (size_t)(rowbase + r0) * 16 + kh * 8;
    const float4* s1 = reinterpret_cast<const float4*>(src) + (size_t)(rowbase + r0 + 8) * 16 + kh * 8;
#pragma unroll
    for (int kk = 0; kk < 4; kk++) {
        const int ks = kh * 4 + kk;
        float4 f0 = s0[kk * 2 + 0], f1 = s0[kk * 2 + 1];
        float4 g0 = s1[kk * 2 + 0], g1 = s1[kk * 2 + 1];
        float4* base = reinterpret_cast<float4*>(dst) + ((ks * 8 + blk) * 32 + q);
        base[0 * 8] = make_float4(f0.x, f1.x, g0.x, g1.x);
        base[1 * 8] = make_float4(f0.y, f1.y, g0.y, g1.y);
        base[2 * 8] = make_float4(f0.z, f1.z, g0.z, g1.z);
        base[3 * 8] = make_float4(f0.w, f1.w, g0.w, g1.w);
    }
}

// ---------------------------------------------------------------------------
// Main kernel.
// ---------------------------------------------------------------------------
__global__ __launch_bounds__(256, 1)
void dist_kernel() {
    extern __shared__ float smf[];
    const int tid = threadIdx.x;
    const int wid = tid >> 5;
    const int lane = tid & 31;
    const int rowbase = blockIdx.x * BM;

    // ---- phase 1: A main fill (threads 0-127), zero pad regions (threads 128-255)
    if (tid < 128) {
        fill_tile(smf, g_atf, rowbase, tid);
    } else {
        const int z = tid - 128;
        // pad regions: ks=8 of A and both B stages, 1024 floats each
        for (int i = z; i < 256; i += 128) {                 // 256 float4 per region
            reinterpret_cast<float4*>(smf + 8192)[i]              = make_float4(0, 0, 0, 0);
            reinterpret_cast<float4*>(smf + BSTART + 8192)[i]     = make_float4(0, 0, 0, 0);
            reinterpret_cast<float4*>(smf + BSTART + STAGEF + 8192)[i] = make_float4(0, 0, 0, 0);
        }
    }
    __syncthreads();

    // ---- phase 2: A pad ones (threads 0-127), producers fill B tile 0 stage 0
    if (tid < 128) {
        const int r = tid;
        const int r_in = r & 15;
        smf[((64 + (r >> 4)) * 32 + (r_in & 7)) * 4 + (r_in >> 3) * 2] = 1.0f;
    } else {
        const int tsub = tid - 128;
        fill_tile(smf + BSTART, g_btf, 0, tsub);
        if (tsub < 64) {                                      // bsq pad entries for tile 0
            const int q = tsub & 7, blk = tsub >> 3;
            const int n0 = blk * 16 + q;
            float* u = smf + BSTART + ((64 + blk) * 32 + q) * 4;
            u[0] = g_bsq[n0];
            u[2] = g_bsq[n0 + 8];
        }
    }
    __syncthreads();

    // ---- main pipeline
    const int wm = wid >> 1;            // 0..1 (rows wm*64)
    const int wn = wid & 1;             // 0..1 (cols wn*64)
    const int pu = (lane & 3) * 8 + (lane >> 2);   // fragment unit permutation

    float acc[4][8][4];
    float m[8];
#pragma unroll
    for (int i = 0; i < 8; i++) m[i] = 3.4e38f;

    for (int t = 0; t < NTILES; t++) {
        if (tid < 128) {
            const float* Bs = smf + BSTART + (t & 1) * STAGEF;
            uint4 av[4], bv[4];
            // ks = 0 (accumulator init via zero-C mma)
#pragma unroll
            for (int i = 0; i < 4; i++) {
                av[i] = *reinterpret_cast<const uint4*>(smf + ((wm * 4 + i) * 32 + pu) * 4);
                bv[i] = *reinterpret_cast<const uint4*>(Bs + ((wn * 4 + i) * 32 + pu) * 4);
            }
#pragma unroll
            for (int mt = 0; mt < 4; mt++)
#pragma unroll
                for (int p = 0; p < 4; p++) {
                    mma_zero(acc[mt][2 * p][0], acc[mt][2 * p][1], acc[mt][2 * p][2], acc[mt][2 * p][3],
                             av[mt].x, av[mt].z, av[mt].y, av[mt].w, bv[p].x, bv[p].y);
                    mma_zero(acc[mt][2 * p + 1][0], acc[mt][2 * p + 1][1], acc[mt][2 * p + 1][2], acc[mt][2 * p + 1][3],
                             av[mt].x, av[mt].z, av[mt].y, av[mt].w, bv[p].z, bv[p].w);
                }
#pragma unroll
            for (int ks = 1; ks < KSTEPS; ks++) {
#pragma unroll
                for (int i = 0; i < 4; i++) {
                    av[i] = *reinterpret_cast<const uint4*>(smf + ((ks * 8 + wm * 4 + i) * 32 + pu) * 4);
                    bv[i] = *reinterpret_cast<const uint4*>(Bs + ((ks * 8 + wn * 4 + i) * 32 + pu) * 4);
                }
#pragma unroll
                for (int mt = 0; mt < 4; mt++)
#pragma unroll
                    for (int p = 0; p < 4; p++) {
                        mma_acc(acc[mt][2 * p][0], acc[mt][2 * p][1], acc[mt][2 * p][2], acc[mt][2 * p][3],
                                av[mt].x, av[mt].z, av[mt].y, av[mt].w, bv[p].x, bv[p].y);
                        mma_acc(acc[mt][2 * p + 1][0], acc[mt][2 * p + 1][1], acc[mt][2 * p + 1][2], acc[mt][2 * p + 1][3],
                                av[mt].x, av[mt].z, av[mt].y, av[mt].w, bv[p].z, bv[p].w);
                    }
            }
            // fold into running row minima
#pragma unroll
            for (int mt = 0; mt < 4; mt++)
#pragma unroll
                for (int nt = 0; nt < 8; nt++) {
                    m[mt * 2 + 0] = fminf(m[mt * 2 + 0], fminf(acc[mt][nt][0], acc[mt][nt][1]));
                    m[mt * 2 + 1] = fminf(m[mt * 2 + 1], fminf(acc[mt][nt][2], acc[mt][nt][3]));
                }
        } else if (t + 1 < NTILES) {
            const int tsub = tid - 128;
            float* stage = smf + BSTART + ((t + 1) & 1) * STAGEF;
            fill_tile(stage, g_btf, (t + 1) * BN, tsub);
            if (tsub < 64) {
                const int q = tsub & 7, blk = tsub >> 3;
                const int n0 = (t + 1) * BN + blk * 16 + q;
                float* u = stage + ((64 + blk) * 32 + q) * 4;
                u[0] = g_bsq[n0];
                u[2] = g_bsq[n0 + 8];
            }
        }
        __syncthreads();
    }

    // ---- reduce row minima
    float* red = smf + REDF;
    if (tid < 128) {
#pragma unroll
        for (int i = 0; i < 8; i++) {
            m[i] = fminf(m[i], __shfl_xor_sync(0xffffffffu, m[i], 1));
            m[i] = fminf(m[i], __shfl_xor_sync(0xffffffffu, m[i], 2));
        }
    }
    if (tid < 128 && wn == 0 && (lane & 3) == 0) {
#pragma unroll
        for (int mt = 0; mt < 4; mt++) {
            int r0 = wm * 64 + mt * 16 + (lane >> 2);
            red[r0]     = m[2 * mt + 0];
            red[r0 + 8] = m[2 * mt + 1];
        }
    }
    __syncthreads();
    if (tid < 128 && wn == 1 && (lane & 3) == 0) {
#pragma unroll
        for (int mt = 0; mt < 4; mt++) {
            int r0 = wm * 64 + mt * 16 + (lane >> 2);
            red[r0]     = fminf(red[r0],     m[2 * mt + 0]);
            red[r0 + 8] = fminf(red[r0 + 8], m[2 * mt + 1]);
        }
    }
    __syncthreads();

    float v = 0.f;
    if (tid < 128) v = red[tid] + g_asq[rowbase + tid];
#pragma unroll
    for (int msk = 16; msk; msk >>= 1) v += __shfl_xor_sync(0xffffffffu, v, msk);
    if (lane == 0) red[128 + wid] = v;
    __syncthreads();
    if (tid == 0) {
        float s = 0.f;
#pragma unroll
        for (int i = 0; i < 8; i++) s += red[128 + i];
        g_bsum[blockIdx.x] = s;
    }
}

// ---------------------------------------------------------------------------
// Deterministic final reduction.
// ---------------------------------------------------------------------------
__global__ void final_reduce_kernel(float* __restrict__ out) {
    int lane = threadIdx.x;
    float v = 0.f;
#pragma unroll
    for (int i = 0; i < NBLK / 32; i++) v += g_bsum[lane + i * 32];
#pragma unroll
    for (int msk = 16; msk; msk >>= 1) v += __shfl_xor_sync(0xffffffffu, v, msk);
    if (lane == 0) out[0] = v;
}

extern "C" void kernel_launch(void* const* d_in, const int* in_sizes, int n_in,
                              void* d_out, int out_size) {
    const float* A = (const float*)d_in[0];
    const float* B = (const float*)d_in[1];
    float* out = (float*)d_out;

    cudaFuncSetAttribute(dist_kernel, cudaFuncAttributeMaxDynamicSharedMemorySize, SMEM_BYTES);

    prep_kernel<<<(2 * NPTS) / 256, 256>>>(A, B);
    dist_kernel<<<NBLK, 256, SMEM_BYTES>>>();
    final_reduce_kernel<<<1, 32>>>(out);
}

// round 4
// speedup vs baseline: 5.5815x; 3.4375x over previous
#include <cuda_runtime.h>
#include <cuda_fp16.h>
#include <cstdint>

// SimpleDistanceLoss:
//   approx search: S[m][n] = bsq[n] - 2<a_m,b_n>  via fp16 m16n8k16 mma.sync
//   (bsq folded into the C-operand of the first k-step; index packed into low
//    7 mantissa bits for argmin tracking)
//   exact pass:   per-row winner recomputed as sum((a-b)^2) in fp32.

#define NPTS   16384
#define DDIM   64
#define NTILES 128
#define NBLK   128

__device__ uint4 g_aunits[NBLK * 1024];   // fragment-unit layout of -2*A (fp16)
__device__ uint4 g_bunits[NTILES * 1024]; // fragment-unit layout of B (fp16)
__device__ float g_bsq[NPTS];             // exact fp32 ||b||^2
__device__ float g_bsum[NBLK];

// ---- smem byte offsets (dynamic) ----
#define SM_A     0
#define SM_B0    16384
#define SM_B1    32768
#define SM_BSQ0  49152
#define SM_BSQ1  49664
#define SM_REDV  50176                    // float[128][2]
#define SM_REDT  51200                    // int[128][2]
#define SM_WS    52224                    // float[4]
#define SMEM_BYTES 52352

static __device__ __forceinline__ uint32_t smem_u32(const void* p) {
    uint32_t a;
    asm("{ .reg .u64 t; cvta.to.shared.u64 t, %1; cvt.u32.u64 %0, t; }" : "=r"(a) : "l"(p));
    return a;
}
#define CP16(sm, gp) \
    asm volatile("cp.async.cg.shared.global [%0], [%1], 16;" :: "r"(sm), "l"(gp))
#define CP_COMMIT() asm volatile("cp.async.commit_group;" ::: "memory")
#define CP_WAIT0()  asm volatile("cp.async.wait_group 0;" ::: "memory")

static __device__ __forceinline__ void mma_acc(float c[4], uint32_t a0, uint32_t a1,
                                               uint32_t a2, uint32_t a3,
                                               uint32_t b0, uint32_t b1) {
    asm("mma.sync.aligned.m16n8k16.row.col.f32.f16.f16.f32 "
        "{%0,%1,%2,%3},{%4,%5,%6,%7},{%8,%9},{%0,%1,%2,%3};"
        : "+f"(c[0]), "+f"(c[1]), "+f"(c[2]), "+f"(c[3])
        : "r"(a0), "r"(a1), "r"(a2), "r"(a3), "r"(b0), "r"(b1));
}
static __device__ __forceinline__ void mma_init(float c[4], uint32_t a0, uint32_t a1,
                                                uint32_t a2, uint32_t a3,
                                                uint32_t b0, uint32_t b1,
                                                float ci0, float ci1) {
    asm("mma.sync.aligned.m16n8k16.row.col.f32.f16.f16.f32 "
        "{%0,%1,%2,%3},{%4,%5,%6,%7},{%8,%9},{%10,%11,%10,%11};"
        : "=f"(c[0]), "=f"(c[1]), "=f"(c[2]), "=f"(c[3])
        : "r"(a0), "r"(a1), "r"(a2), "r"(a3), "r"(b0), "r"(b1), "f"(ci0), "f"(ci1));
}

// ---------------------------------------------------------------------------
// Prep: fp32 -> fp16 (A scaled by -2), repack into MMA fragment-unit layout,
// compute exact bsq. Block b<128: A tile b; b>=128: B tile b-128.
// Unit (ks, blk, s): 8 halfs {X[x][k],X[x][k+1], X[x+8][k],X[x+8][k+1],
//                            X[x][k+8],X[x][k+9], X[x+8][k+8],X[x+8][k+9]}
// with x = blk*16 + (s>>2), k = ks*16 + (s&3)*2.  Matches m16n8k16 frags.
// ---------------------------------------------------------------------------
__global__ __launch_bounds__(256)
void prep_kernel(const float* __restrict__ A, const float* __restrict__ B) {
    __shared__ __half sh[128 * 64];
    __shared__ float nr[256];
    const int tid = threadIdx.x;
    const bool isB = blockIdx.x >= NBLK;
    const int tile = blockIdx.x & (NBLK - 1);
    const float sc = isB ? 1.0f : -2.0f;

    const float4* s4 = reinterpret_cast<const float4*>(isB ? B : A) + (size_t)tile * 128 * 16;
    const int row = tid & 127, half = tid >> 7;
    float nrm = 0.f;
    half2* sh2 = reinterpret_cast<half2*>(sh);
#pragma unroll
    for (int i = 0; i < 8; i++) {
        float4 v = s4[row * 16 + half * 8 + i];
        nrm += v.x * v.x + v.y * v.y + v.z * v.z + v.w * v.w;
        sh2[row * 32 + half * 16 + i * 2 + 0] = __floats2half2_rn(sc * v.x, sc * v.y);
        sh2[row * 32 + half * 16 + i * 2 + 1] = __floats2half2_rn(sc * v.z, sc * v.w);
    }
    nr[tid] = nrm;
    __syncthreads();
    if (isB && tid < 128) g_bsq[tile * 128 + tid] = nr[tid] + nr[tid + 128];

    uint4* dst = (isB ? g_bunits : g_aunits) + (size_t)tile * 1024;
#pragma unroll
    for (int i = 0; i < 4; i++) {
        int u = tid + i * 256;
        int ks = u >> 8, blk = (u >> 5) & 7, s = u & 31;
        int x = blk * 16 + (s >> 2), k = ks * 16 + (s & 3) * 2;
        const uint32_t* p0 = reinterpret_cast<const uint32_t*>(&sh[x * 64 + k]);
        const uint32_t* p1 = reinterpret_cast<const uint32_t*>(&sh[(x + 8) * 64 + k]);
        uint4 v;
        v.x = p0[0]; v.y = p1[0]; v.z = p0[4]; v.w = p1[4];
        dst[u] = v;
    }
}

// ---------------------------------------------------------------------------
// Main kernel: 128 CTAs x 256 threads, all 8 warps compute (warp tile 32x64).
// ---------------------------------------------------------------------------
__global__ __launch_bounds__(256, 1)
void dist_kernel(const float* __restrict__ A, const float* __restrict__ B) {
    extern __shared__ char sm[];
    const uint32_t smb = smem_u32(sm);
    const int tid = threadIdx.x;
    const int wid = tid >> 5, lane = tid & 31;
    const int wm = wid & 3, wn = wid >> 2;     // rows wm*32, cols wn*64
    const int rowbase = blockIdx.x * 128;
    const int idxbase = wn * 64 + (lane & 3) * 2;

    // ---- prologue: A units + B tile 0 + bsq tile 0 ----
    {
        const uint4* gA = g_aunits + (size_t)blockIdx.x * 1024;
        const uint4* gB = g_bunits;
#pragma unroll
        for (int i = 0; i < 4; i++) {
            int u = tid + i * 256;
            CP16(smb + SM_A + u * 16, gA + u);
            CP16(smb + SM_B0 + u * 16, gB + u);
        }
        if (tid < 32) CP16(smb + SM_BSQ0 + tid * 16, reinterpret_cast<const uint4*>(g_bsq) + tid);
        CP_COMMIT();
        CP_WAIT0();
        __syncthreads();
    }

    const uint4* Au = reinterpret_cast<const uint4*>(sm + SM_A);
    float pmin[4];
    int ptile[4];
#pragma unroll
    for (int s = 0; s < 4; s++) { pmin[s] = 3.4e38f; ptile[s] = 0; }

    for (int t = 0; t < NTILES; t++) {
        // prefetch next tile into the other stage
        if (t + 1 < NTILES) {
            const uint4* gB = g_bunits + (size_t)(t + 1) * 1024;
            const uint32_t dstB = smb + ((t & 1) ? SM_B0 : SM_B1);
#pragma unroll
            for (int i = 0; i < 4; i++) {
                int u = tid + i * 256;
                CP16(dstB + u * 16, gB + u);
            }
            if (tid < 32)
                CP16(smb + ((t & 1) ? SM_BSQ0 : SM_BSQ1) + tid * 16,
                     reinterpret_cast<const uint4*>(g_bsq + (t + 1) * 128) + tid);
            CP_COMMIT();
        }

        const uint4* Bu = reinterpret_cast<const uint4*>(sm + ((t & 1) ? SM_B1 : SM_B0));
        const float* bsqs = reinterpret_cast<const float*>(sm + ((t & 1) ? SM_BSQ1 : SM_BSQ0));

        float2 bq[8];
#pragma unroll
        for (int p = 0; p < 4; p++)
#pragma unroll
            for (int h = 0; h < 2; h++)
                bq[p * 2 + h] = *reinterpret_cast<const float2*>(&bsqs[idxbase + p * 16 + h * 8]);

        float acc[2][8][4];
#pragma unroll
        for (int ks = 0; ks < 4; ks++) {
            uint4 af[2], bf[4];
#pragma unroll
            for (int mt = 0; mt < 2; mt++)
                af[mt] = Au[(ks * 8 + wm * 2 + mt) * 32 + lane];
#pragma unroll
            for (int p = 0; p < 4; p++)
                bf[p] = Bu[(ks * 8 + wn * 4 + p) * 32 + lane];
#pragma unroll
            for (int mt = 0; mt < 2; mt++)
#pragma unroll
                for (int p = 0; p < 4; p++) {
                    if (ks == 0) {
                        mma_init(acc[mt][2 * p],     af[mt].x, af[mt].y, af[mt].z, af[mt].w,
                                 bf[p].x, bf[p].z, bq[2 * p].x, bq[2 * p].y);
                        mma_init(acc[mt][2 * p + 1], af[mt].x, af[mt].y, af[mt].z, af[mt].w,
                                 bf[p].y, bf[p].w, bq[2 * p + 1].x, bq[2 * p + 1].y);
                    } else {
                        mma_acc(acc[mt][2 * p],     af[mt].x, af[mt].y, af[mt].z, af[mt].w,
                                bf[p].x, bf[p].z);
                        mma_acc(acc[mt][2 * p + 1], af[mt].x, af[mt].y, af[mt].z, af[mt].w,
                                bf[p].y, bf[p].w);
                    }
                }
        }

        // pack in-tile col index into low 7 mantissa bits, fold running minima
#pragma unroll
        for (int mt = 0; mt < 2; mt++)
#pragma unroll
            for (int hi = 0; hi < 2; hi++) {
                const int slot = mt * 2 + hi;
                float tm = 3.4e38f;
#pragma unroll
                for (int j = 0; j < 8; j++)
#pragma unroll
                    for (int c = 0; c < 2; c++) {
                        float v = acc[mt][j][hi * 2 + c];
                        int tc = idxbase + (j >> 1) * 16 + (j & 1) * 8 + c;
                        float pf = __uint_as_float((__float_as_uint(v) & 0xFFFFFF80u) |
                                                   (unsigned)tc);
                        tm = fminf(tm, pf);
                    }
                if (tm < pmin[slot]) { pmin[slot] = tm; ptile[slot] = t; }
            }

        CP_WAIT0();
        __syncthreads();
    }

    // ---- reduce winners across the 4 lanes sharing each row ----
    float* redv = reinterpret_cast<float*>(sm + SM_REDV);
    int*   redt = reinterpret_cast<int*>(sm + SM_REDT);
#pragma unroll
    for (int slot = 0; slot < 4; slot++) {
        float v = pmin[slot];
        int tt = ptile[slot];
#pragma unroll
        for (int mk = 1; mk <= 2; mk <<= 1) {
            float ov = __shfl_xor_sync(0xffffffffu, v, mk);
            int ot = __shfl_xor_sync(0xffffffffu, tt, mk);
            if (ov < v) { v = ov; tt = ot; }
        }
        if ((lane & 3) == 0) {
            int row = wm * 32 + (slot >> 1) * 16 + (lane >> 2) + (slot & 1) * 8;
            redv[row * 2 + wn] = v;
            redt[row * 2 + wn] = tt;
        }
    }
    __syncthreads();

    // ---- exact fp32 recompute of each row's winner, then block sum ----
    float* ws = reinterpret_cast<float*>(sm + SM_WS);
    if (tid < 128) {
        float v0 = redv[tid * 2 + 0], v1 = redv[tid * 2 + 1];
        int sel = (v1 < v0) ? 1 : 0;
        float pv = sel ? v1 : v0;
        int tt = redt[tid * 2 + sel];
        int colg = tt * 128 + (int)(__float_as_uint(pv) & 0x7Fu);

        const float4* ar = reinterpret_cast<const float4*>(A) + (size_t)(rowbase + tid) * 16;
        const float4* br = reinterpret_cast<const float4*>(B) + (size_t)colg * 16;
        float s = 0.f;
#pragma unroll
        for (int i = 0; i < 16; i++) {
            float4 a4 = ar[i], b4 = br[i];
            float dx = a4.x - b4.x, dy = a4.y - b4.y, dz = a4.z - b4.z, dw = a4.w - b4.w;
            s += dx * dx + dy * dy + dz * dz + dw * dw;
        }
#pragma unroll
        for (int mk = 16; mk; mk >>= 1) s += __shfl_xor_sync(0xffffffffu, s, mk);
        if (lane == 0) ws[wid] = s;
    }
    __syncthreads();
    if (tid == 0) g_bsum[blockIdx.x] = ws[0] + ws[1] + ws[2] + ws[3];
}

// ---------------------------------------------------------------------------
__global__ void final_reduce_kernel(float* __restrict__ out) {
    int lane = threadIdx.x;
    float v = 0.f;
#pragma unroll
    for (int i = 0; i < NBLK / 32; i++) v += g_bsum[lane + i * 32];
#pragma unroll
    for (int mk = 16; mk; mk >>= 1) v += __shfl_xor_sync(0xffffffffu, v, mk);
    if (lane == 0) out[0] = v;
}

extern "C" void kernel_launch(void* const* d_in, const int* in_sizes, int n_in,
                              void* d_out, int out_size) {
    const float* A = (const float*)d_in[0];
    const float* B = (const float*)d_in[1];
    float* out = (float*)d_out;

    cudaFuncSetAttribute(dist_kernel, cudaFuncAttributeMaxDynamicSharedMemorySize, SMEM_BYTES);

    prep_kernel<<<2 * NBLK, 256>>>(A, B);
    dist_kernel<<<NBLK, 256, SMEM_BYTES>>>(A, B);
    final_reduce_kernel<<<1, 32>>>(out);
}

// round 5
// speedup vs baseline: 6.6849x; 1.1977x over previous
#include <cuda_runtime.h>
#include <cuda_fp16.h>
#include <cstdint>

// SimpleDistanceLoss:
//   search: S[m][n] = bsq[n] - 2<a_m,b_n> via fp16 m16n8k16 mma.sync with
//           *fp16 accumulators* (2x rate vs f32 accum). bsq folded into the
//           C operand of the first k-step. Search tracks only the winning
//           candidate GROUP (tile, col-half, lane-pair, parity) per row.
//   tail:   exact fp32 recompute over the 8 candidate columns of the winning
//           group; min of those is the row's nearest-neighbor distance.

#define NPTS   16384
#define DDIM   64
#define NTILES 128
#define NBLK   128

__device__ uint4 g_aunits[NBLK * 1024];    // fragment-unit layout of -2*A (fp16)
__device__ uint4 g_bunits[NTILES * 1024];  // fragment-unit layout of B (fp16)
__device__ __align__(16) __half g_bsqh[NPTS];  // fp16 ||b||^2
__device__ float g_bsum[NBLK];

// ---- smem byte offsets ----
#define SM_A     0
#define SM_B0    16384
#define SM_B1    32768
#define SM_BSQ0  49152                     // 256 B (128 halfs)
#define SM_BSQ1  49408
#define SM_REDV  49664                     // float[128][2]
#define SM_REDM  50688                     // int[128][2]
#define SM_WS    51712                     // float[4]
#define SMEM_BYTES 51840

static __device__ __forceinline__ uint32_t smem_u32(const void* p) {
    uint32_t a;
    asm("{ .reg .u64 t; cvta.to.shared.u64 t, %1; cvt.u32.u64 %0, t; }" : "=r"(a) : "l"(p));
    return a;
}
#define CP16(sm, gp) \
    asm volatile("cp.async.cg.shared.global [%0], [%1], 16;" :: "r"(sm), "l"(gp))
#define CP_COMMIT() asm volatile("cp.async.commit_group;" ::: "memory")
#define CP_WAIT0()  asm volatile("cp.async.wait_group 0;" ::: "memory")

// fp16-accumulator MMA: D,C are 2 b32 regs (f16x2).
static __device__ __forceinline__ void mma_h_acc(uint32_t c[2], uint32_t a0, uint32_t a1,
                                                 uint32_t a2, uint32_t a3,
                                                 uint32_t b0, uint32_t b1) {
    asm("mma.sync.aligned.m16n8k16.row.col.f16.f16.f16.f16 "
        "{%0,%1},{%2,%3,%4,%5},{%6,%7},{%0,%1};"
        : "+r"(c[0]), "+r"(c[1])
        : "r"(a0), "r"(a1), "r"(a2), "r"(a3), "r"(b0), "r"(b1));
}
static __device__ __forceinline__ void mma_h_init(uint32_t c[2], uint32_t a0, uint32_t a1,
                                                  uint32_t a2, uint32_t a3,
                                                  uint32_t b0, uint32_t b1, uint32_t bq) {
    asm("mma.sync.aligned.m16n8k16.row.col.f16.f16.f16.f16 "
        "{%0,%1},{%2,%3,%4,%5},{%6,%7},{%8,%8};"
        : "=r"(c[0]), "=r"(c[1])
        : "r"(a0), "r"(a1), "r"(a2), "r"(a3), "r"(b0), "r"(b1), "r"(bq));
}

// ---------------------------------------------------------------------------
// Prep: fp32 -> fp16 (A scaled by -2), repack into MMA fragment-unit layout,
// compute bsq (fp16). Block b<128: A tile b; b>=128: B tile b-128.
// Unit (ks, blk, s): 8 halfs {X[x][k],X[x][k+1], X[x+8][k],X[x+8][k+1],
//                             X[x][k+8],X[x][k+9], X[x+8][k+8],X[x+8][k+9]}
// with x = blk*16 + (s>>2), k = ks*16 + (s&3)*2.
// ---------------------------------------------------------------------------
__global__ __launch_bounds__(256)
void prep_kernel(const float* __restrict__ A, const float* __restrict__ B) {
    __shared__ __half sh[128 * 64];
    __shared__ float nr[256];
    const int tid = threadIdx.x;
    const bool isB = blockIdx.x >= NBLK;
    const int tile = blockIdx.x & (NBLK - 1);
    const float sc = isB ? 1.0f : -2.0f;

    const float4* s4 = reinterpret_cast<const float4*>(isB ? B : A) + (size_t)tile * 128 * 16;
    const int row = tid & 127, hf = tid >> 7;
    float nrm = 0.f;
    half2* sh2 = reinterpret_cast<half2*>(sh);
#pragma unroll
    for (int i = 0; i < 8; i++) {
        float4 v = s4[row * 16 + hf * 8 + i];
        nrm += v.x * v.x + v.y * v.y + v.z * v.z + v.w * v.w;
        sh2[row * 32 + hf * 16 + i * 2 + 0] = __floats2half2_rn(sc * v.x, sc * v.y);
        sh2[row * 32 + hf * 16 + i * 2 + 1] = __floats2half2_rn(sc * v.z, sc * v.w);
    }
    nr[tid] = nrm;
    __syncthreads();
    if (isB && tid < 128) g_bsqh[tile * 128 + tid] = __float2half_rn(nr[tid] + nr[tid + 128]);

    uint4* dst = (isB ? g_bunits : g_aunits) + (size_t)tile * 1024;
#pragma unroll
    for (int i = 0; i < 4; i++) {
        int u = tid + i * 256;
        int ks = u >> 8, blk = (u >> 5) & 7, s = u & 31;
        int x = blk * 16 + (s >> 2), k = ks * 16 + (s & 3) * 2;
        const uint32_t* p0 = reinterpret_cast<const uint32_t*>(&sh[x * 64 + k]);
        const uint32_t* p1 = reinterpret_cast<const uint32_t*>(&sh[(x + 8) * 64 + k]);
        uint4 v;
        v.x = p0[0]; v.y = p1[0]; v.z = p0[4]; v.w = p1[4];
        dst[u] = v;
    }
}

// ---------------------------------------------------------------------------
// Main: 128 CTAs x 256 threads, all 8 warps compute (warp tile 32x64).
// ---------------------------------------------------------------------------
__global__ __launch_bounds__(256, 1)
void dist_kernel(const float* __restrict__ A, const float* __restrict__ B) {
    extern __shared__ char sm[];
    const uint32_t smb = smem_u32(sm);
    const int tid = threadIdx.x;
    const int wid = tid >> 5, lane = tid & 31;
    const int wm = wid & 3, wn = wid >> 2;     // rows wm*32, cols wn*64
    const int rowbase = blockIdx.x * 128;
    const int idxbase = wn * 64 + (lane & 3) * 2;

    // ---- prologue: A units + B tile 0 + bsq tile 0 ----
    {
        const uint4* gA = g_aunits + (size_t)blockIdx.x * 1024;
        const uint4* gB = g_bunits;
#pragma unroll
        for (int i = 0; i < 4; i++) {
            int u = tid + i * 256;
            CP16(smb + SM_A + u * 16, gA + u);
            CP16(smb + SM_B0 + u * 16, gB + u);
        }
        if (tid < 16) CP16(smb + SM_BSQ0 + tid * 16, reinterpret_cast<const uint4*>(g_bsqh) + tid);
        CP_COMMIT();
        CP_WAIT0();
        __syncthreads();
    }

    const uint4* Au = reinterpret_cast<const uint4*>(sm + SM_A);
    float pmin[8];
    int ptile[8];
#pragma unroll
    for (int s = 0; s < 8; s++) { pmin[s] = 3.4e38f; ptile[s] = 0; }

    for (int t = 0; t < NTILES; t++) {
        if (t + 1 < NTILES) {
            const uint4* gB = g_bunits + (size_t)(t + 1) * 1024;
            const uint32_t dstB = smb + ((t & 1) ? SM_B0 : SM_B1);
#pragma unroll
            for (int i = 0; i < 4; i++) {
                int u = tid + i * 256;
                CP16(dstB + u * 16, gB + u);
            }
            if (tid < 16)
                CP16(smb + ((t & 1) ? SM_BSQ0 : SM_BSQ1) + tid * 16,
                     reinterpret_cast<const uint4*>(g_bsqh + (t + 1) * 128) + tid);
            CP_COMMIT();
        }

        const uint4* Bu = reinterpret_cast<const uint4*>(sm + ((t & 1) ? SM_B1 : SM_B0));
        const char* bsqs = sm + ((t & 1) ? SM_BSQ1 : SM_BSQ0);

        uint32_t bq[8];
#pragma unroll
        for (int j = 0; j < 8; j++)
            bq[j] = *reinterpret_cast<const uint32_t*>(
                bsqs + (idxbase + (j >> 1) * 16 + (j & 1) * 8) * 2);

        uint32_t acc[2][8][2];
#pragma unroll
        for (int ks = 0; ks < 4; ks++) {
            uint4 af[2], bf[4];
#pragma unroll
            for (int mt = 0; mt < 2; mt++)
                af[mt] = Au[(ks * 8 + wm * 2 + mt) * 32 + lane];
#pragma unroll
            for (int p = 0; p < 4; p++)
                bf[p] = Bu[(ks * 8 + wn * 4 + p) * 32 + lane];
#pragma unroll
            for (int mt = 0; mt < 2; mt++)
#pragma unroll
                for (int p = 0; p < 4; p++) {
                    if (ks == 0) {
                        mma_h_init(acc[mt][2 * p],     af[mt].x, af[mt].y, af[mt].z, af[mt].w,
                                   bf[p].x, bf[p].z, bq[2 * p]);
                        mma_h_init(acc[mt][2 * p + 1], af[mt].x, af[mt].y, af[mt].z, af[mt].w,
                                   bf[p].y, bf[p].w, bq[2 * p + 1]);
                    } else {
                        mma_h_acc(acc[mt][2 * p],     af[mt].x, af[mt].y, af[mt].z, af[mt].w,
                                  bf[p].x, bf[p].z);
                        mma_h_acc(acc[mt][2 * p + 1], af[mt].x, af[mt].y, af[mt].z, af[mt].w,
                                  bf[p].y, bf[p].w);
                    }
                }
        }

        // fold tile minimum per (mt, row-half) slot across the 8 j-blocks
#pragma unroll
        for (int mt = 0; mt < 2; mt++)
#pragma unroll
            for (int rh = 0; rh < 2; rh++) {
                __half2 mn = *reinterpret_cast<__half2*>(&acc[mt][0][rh]);
#pragma unroll
                for (int j = 1; j < 8; j++)
                    mn = __hmin2(mn, *reinterpret_cast<__half2*>(&acc[mt][j][rh]));
                float2 f = __half22float2(mn);
                const int s = mt * 2 + rh;
                if (f.x < pmin[2 * s + 0]) { pmin[2 * s + 0] = f.x; ptile[2 * s + 0] = t; }
                if (f.y < pmin[2 * s + 1]) { pmin[2 * s + 1] = f.y; ptile[2 * s + 1] = t; }
            }

        CP_WAIT0();
        __syncthreads();
    }

    // ---- per-row winner (group) across parity, lanes, wn-halves ----
    float* redv = reinterpret_cast<float*>(sm + SM_REDV);
    int*   redm = reinterpret_cast<int*>(sm + SM_REDM);
#pragma unroll
    for (int s = 0; s < 4; s++) {
        float v0 = pmin[2 * s], v1 = pmin[2 * s + 1];
        int h = (v1 < v0) ? 1 : 0;
        float v = h ? v1 : v0;
        int meta = (ptile[2 * s + h] << 4) | (wn << 3) | ((lane & 3) * 2 + h);
#pragma unroll
        for (int mk = 1; mk <= 2; mk <<= 1) {
            float ov = __shfl_xor_sync(0xffffffffu, v, mk);
            int om = __shfl_xor_sync(0xffffffffu, meta, mk);
            if (ov < v) { v = ov; meta = om; }
        }
        if ((lane & 3) == 0) {
            int row = wm * 32 + (s >> 1) * 16 + (s & 1) * 8 + (lane >> 2);
            redv[row * 2 + wn] = v;
            redm[row * 2 + wn] = meta;
        }
    }
    __syncthreads();

    // ---- exact fp32 recompute over the 8 candidate columns of the winner ----
    float* ws = reinterpret_cast<float*>(sm + SM_WS);
    if (tid < 128) {
        float v0 = redv[tid * 2 + 0], v1 = redv[tid * 2 + 1];
        int sel = (v1 < v0) ? 1 : 0;
        int meta = redm[tid * 2 + sel];
        int base = (meta >> 4) * 128 + ((meta >> 3) & 1) * 64 + (meta & 7);

        const float4* ar = reinterpret_cast<const float4*>(A) + (size_t)(rowbase + tid) * 16;
        float4 a4[16];
#pragma unroll
        for (int i = 0; i < 16; i++) a4[i] = ar[i];

        float best = 3.4e38f;
#pragma unroll
        for (int jj = 0; jj < 8; jj++) {
            const float4* br = reinterpret_cast<const float4*>(B) + (size_t)(base + jj * 8) * 16;
            float s = 0.f;
#pragma unroll
            for (int i = 0; i < 16; i++) {
                float4 b4 = br[i];
                float dx = a4[i].x - b4.x, dy = a4[i].y - b4.y;
                float dz = a4[i].z - b4.z, dw = a4[i].w - b4.w;
                s += dx * dx + dy * dy + dz * dz + dw * dw;
            }
            best = fminf(best, s);
        }
#pragma unroll
        for (int mk = 16; mk; mk >>= 1) best += __shfl_xor_sync(0xffffffffu, best, mk);
        if (lane == 0) ws[wid] = best;
    }
    __syncthreads();
    if (tid == 0) g_bsum[blockIdx.x] = ws[0] + ws[1] + ws[2] + ws[3];
}

// ---------------------------------------------------------------------------
__global__ void final_reduce_kernel(float* __restrict__ out) {
    int lane = threadIdx.x;
    float v = 0.f;
#pragma unroll
    for (int i = 0; i < NBLK / 32; i++) v += g_bsum[lane + i * 32];
#pragma unroll
    for (int mk = 16; mk; mk >>= 1) v += __shfl_xor_sync(0xffffffffu, v, mk);
    if (lane == 0) out[0] = v;
}

extern "C" void kernel_launch(void* const* d_in, const int* in_sizes, int n_in,
                              void* d_out, int out_size) {
    const float* A = (const float*)d_in[0];
    const float* B = (const float*)d_in[1];
    float* out = (float*)d_out;

    cudaFuncSetAttribute(dist_kernel, cudaFuncAttributeMaxDynamicSharedMemorySize, SMEM_BYTES);

    prep_kernel<<<2 * NBLK, 256>>>(A, B);
    dist_kernel<<<NBLK, 256, SMEM_BYTES>>>(A, B);
    final_reduce_kernel<<<1, 32>>>(out);
}